// round 5
// baseline (speedup 1.0000x reference)
#include <cuda_runtime.h>
#include <cstdint>

#define H       64
#define K       256
#define TILE_M  128
#define TPB     256
#define MARGIN  0.75f
#define BFS     144                     // bf16 row stride in bytes (72 halves)

// ---- dynamic smem layout (bytes) ----
#define OFF_CBF   0                      // C bf16: 256 * 144 = 36864
#define OFF_XBF   36864                  // X bf16: 128 * 144 = 18432
#define OFF_CF32  55296                  // C fp32: 256 * 64 * 4 = 65536
#define OFF_XF32  120832                 // X fp32 double buffer: 2 * 32768
#define OFF_C2    186368                 // ||c||^2: 256 * 4
#define SMEM_TOTAL (OFF_C2 + 1024)

__device__ __forceinline__ uint32_t smem_u32(const void* p) {
    uint32_t a;
    asm("{ .reg .u64 t; cvta.to.shared.u64 t, %1; cvt.u32.u64 %0, t; }" : "=r"(a) : "l"(p));
    return a;
}

__device__ __forceinline__ uint32_t bf16x2_pack(float lo, float hi) {
    uint32_t r;
    asm("cvt.rn.bf16x2.f32 %0, %1, %2;" : "=r"(r) : "f"(hi), "f"(lo));
    return r;
}

__device__ __forceinline__ void ldsm4(uint32_t* r, uint32_t addr) {
    asm volatile("ldmatrix.sync.aligned.m8n8.x4.shared.b16 {%0,%1,%2,%3}, [%4];"
        : "=r"(r[0]), "=r"(r[1]), "=r"(r[2]), "=r"(r[3]) : "r"(addr));
}
__device__ __forceinline__ void ldsm2(uint32_t* r, uint32_t addr) {
    asm volatile("ldmatrix.sync.aligned.m8n8.x2.shared.b16 {%0,%1}, [%2];"
        : "=r"(r[0]), "=r"(r[1]) : "r"(addr));
}

__device__ __forceinline__ void mma_bf16(float* d, const uint32_t* a, const uint32_t* b) {
    asm volatile("mma.sync.aligned.m16n8k16.row.col.f32.bf16.bf16.f32 "
        "{%0,%1,%2,%3}, {%4,%5,%6,%7}, {%8,%9}, {%0,%1,%2,%3};"
        : "+f"(d[0]), "+f"(d[1]), "+f"(d[2]), "+f"(d[3])
        : "r"(a[0]), "r"(a[1]), "r"(a[2]), "r"(a[3]), "r"(b[0]), "r"(b[1]));
}

__device__ __forceinline__ void cp16(uint32_t dst, const void* src) {
    asm volatile("cp.async.cg.shared.global [%0], [%1], 16;" :: "r"(dst), "l"(src));
}

extern __shared__ char smem_raw[];

__global__ __launch_bounds__(TPB, 1)
void LatentSpaceClustering_46797963657837_kernel(const float* __restrict__ x,
                                                 const float* __restrict__ c,
                                                 float* __restrict__ out,
                                                 int n, int num_tiles) {
    const uint32_t sbase = smem_u32(smem_raw);
    float* cf32 = (float*)(smem_raw + OFF_CF32);
    float* c2f  = (float*)(smem_raw + OFF_C2);
    const int tid = threadIdx.x;
    const int lane = tid & 31, w = tid >> 5;
    const int groupID = lane >> 2, tig = lane & 3;

    // ---- stage centers: bf16 padded rows + fp32 ----
    {
        const float4* c4 = (const float4*)c;
        for (int j = tid; j < K * H / 4; j += TPB) {        // 4096 float4
            float4 v = c4[j];
            int k = j >> 4, h = (j & 15) << 2;              // h = half index base
            float* r = cf32 + k * H + h;
            r[0] = v.x; r[1] = v.y; r[2] = v.z; r[3] = v.w;
            uint2 p = make_uint2(bf16x2_pack(v.x, v.y), bf16x2_pack(v.z, v.w));
            *(uint2*)(smem_raw + OFF_CBF + k * BFS + h * 2) = p;
        }
    }
    __syncthreads();
    {   // ||c_k||^2, fp32 sequential mul+add (reference-style)
        int k = tid;  // TPB == K
        float s = 0.f;
        const float* r = cf32 + k * H;
        #pragma unroll
        for (int h = 0; h < H; ++h) s = __fadd_rn(s, __fmul_rn(r[h], r[h]));
        c2f[k] = s;
    }

    // ---- prefetch first tile (buf 0) ----
    int buf = 0;
    {
        int tile0 = blockIdx.x;
        long long base_pt = (long long)tile0 * TILE_M;
        #pragma unroll
        for (int i = 0; i < 8; ++i) {
            int chunk = i * TPB + tid;                       // 2048 chunks of 16B
            int row = chunk >> 4, seg = chunk & 15;
            if (base_pt + row < n)
                cp16(sbase + OFF_XF32 + chunk * 16, x + (base_pt + row) * H + seg * 4);
        }
        asm volatile("cp.async.commit_group;");
    }

    // per-lane ldmatrix address bases
    const uint32_t a_base = sbase + OFF_XBF + (w * 16 + (lane & 15)) * BFS + ((lane >> 4) * 16);
    const uint32_t b_base = sbase + OFF_CBF + (lane & 7) * BFS + (((lane >> 3) & 1) * 16);

    for (int tile = blockIdx.x; tile < num_tiles; tile += gridDim.x) {
        const long long base_pt = (long long)tile * TILE_M;
        asm volatile("cp.async.wait_group 0;" ::: "memory");
        __syncthreads();

        // ---- convert fp32 -> bf16 padded ----
        const float* xf = (const float*)(smem_raw + OFF_XF32 + buf * 32768);
        for (int i = tid; i < TILE_M * 16; i += TPB) {
            int row = i >> 4, h = (i & 15) << 2;
            const float* r = xf + row * H + h;
            uint2 p = make_uint2(bf16x2_pack(r[0], r[1]), bf16x2_pack(r[2], r[3]));
            *(uint2*)(smem_raw + OFF_XBF + row * BFS + h * 2) = p;
        }
        __syncthreads();

        // ---- prefetch next tile into other buffer ----
        {
            long long nb = (long long)(tile + gridDim.x) * TILE_M;
            if (tile + gridDim.x < num_tiles) {
                #pragma unroll
                for (int i = 0; i < 8; ++i) {
                    int chunk = i * TPB + tid;
                    int row = chunk >> 4, seg = chunk & 15;
                    if (nb + row < n)
                        cp16(sbase + OFF_XF32 + (buf ^ 1) * 32768 + chunk * 16,
                             x + (nb + row) * H + seg * 4);
                }
            }
            asm volatile("cp.async.commit_group;");
        }

        // ---- mma: S[16m x 256n] per warp, 4 k-steps ----
        float acc[128];
        #pragma unroll
        for (int j = 0; j < 128; ++j) acc[j] = 0.f;

        #pragma unroll
        for (int ks = 0; ks < 4; ++ks) {
            uint32_t a[4];
            ldsm4(a, a_base + ks * 32);
            #pragma unroll
            for (int j = 0; j < 32; ++j) {
                uint32_t b[2];
                ldsm2(b, b_base + j * (8 * BFS) + ks * 32);
                mma_bf16(acc + j * 4, a, b);
            }
        }

        // ---- epilogue: transform + screen + exact rescore ----
        float mn0 = 3.402823466e+38f, mn1 = 3.402823466e+38f;
        #pragma unroll
        for (int j = 0; j < 32; ++j) {
            float2 c2v = *(const float2*)(c2f + j * 8 + tig * 2);
            float s0 = __fmaf_rn(-2.f, acc[j*4+0], c2v.x);
            float s1 = __fmaf_rn(-2.f, acc[j*4+1], c2v.y);
            float s2 = __fmaf_rn(-2.f, acc[j*4+2], c2v.x);
            float s3 = __fmaf_rn(-2.f, acc[j*4+3], c2v.y);
            acc[j*4+0] = s0; acc[j*4+1] = s1; acc[j*4+2] = s2; acc[j*4+3] = s3;
            mn0 = fminf(mn0, fminf(s0, s1));
            mn1 = fminf(mn1, fminf(s2, s3));
        }
        #pragma unroll
        for (int off = 1; off <= 2; off <<= 1) {
            mn0 = fminf(mn0, __shfl_xor_sync(0xffffffffu, mn0, off));
            mn1 = fminf(mn1, __shfl_xor_sync(0xffffffffu, mn1, off));
        }
        const float thr0 = mn0 + MARGIN, thr1 = mn1 + MARGIN;

        const int r0 = w * 16 + groupID, r1 = r0 + 8;       // rows within tile
        float bd0 = 3.402823466e+38f, bd1 = 3.402823466e+38f;
        int bk0 = K, bk1 = K;
        #pragma unroll
        for (int j = 0; j < 32; ++j) {
            #pragma unroll
            for (int e = 0; e < 2; ++e) {
                int k = j * 8 + tig * 2 + e;
                if (acc[j*4+e] < thr0) {                    // row r0 candidate
                    const float* xr = xf + r0 * H;
                    const float* cr = cf32 + k * H;
                    float x2 = 0.f, dot = 0.f;
                    #pragma unroll 16
                    for (int h = 0; h < H; ++h) {
                        x2  = __fadd_rn(x2, __fmul_rn(xr[h], xr[h]));
                        dot = __fmaf_rn(xr[h], cr[h], dot);
                    }
                    float d2 = __fmaf_rn(-2.f, dot, __fadd_rn(x2, c2f[k]));
                    if (d2 < bd0 || (d2 == bd0 && k < bk0)) { bd0 = d2; bk0 = k; }
                }
                if (acc[j*4+2+e] < thr1) {                  // row r1 candidate
                    const float* xr = xf + r1 * H;
                    const float* cr = cf32 + k * H;
                    float x2 = 0.f, dot = 0.f;
                    #pragma unroll 16
                    for (int h = 0; h < H; ++h) {
                        x2  = __fadd_rn(x2, __fmul_rn(xr[h], xr[h]));
                        dot = __fmaf_rn(xr[h], cr[h], dot);
                    }
                    float d2 = __fmaf_rn(-2.f, dot, __fadd_rn(x2, c2f[k]));
                    if (d2 < bd1 || (d2 == bd1 && k < bk1)) { bd1 = d2; bk1 = k; }
                }
            }
        }
        #pragma unroll
        for (int off = 1; off <= 2; off <<= 1) {
            float od = __shfl_xor_sync(0xffffffffu, bd0, off);
            int   ok = __shfl_xor_sync(0xffffffffu, bk0, off);
            if (od < bd0 || (od == bd0 && ok < bk0)) { bd0 = od; bk0 = ok; }
            od = __shfl_xor_sync(0xffffffffu, bd1, off);
            ok = __shfl_xor_sync(0xffffffffu, bk1, off);
            if (od < bd1 || (od == bd1 && ok < bk1)) { bd1 = od; bk1 = ok; }
        }
        if (tig == 0) {
            long long g0 = base_pt + r0, g1 = base_pt + r1;
            if (g0 < n) out[g0] = (float)bk0;
            if (g1 < n) out[g1] = (float)bk1;
        }

        buf ^= 1;
    }
}

extern "C" void kernel_launch(void* const* d_in, const int* in_sizes, int n_in,
                              void* d_out, int out_size) {
    const float* x = (const float*)d_in[0];
    const float* c = (const float*)d_in[1];
    int n = in_sizes[0] / H;
    int num_tiles = (n + TILE_M - 1) / TILE_M;

    int sms = 148;
    cudaDeviceGetAttribute(&sms, cudaDevAttrMultiProcessorCount, 0);

    cudaFuncSetAttribute(LatentSpaceClustering_46797963657837_kernel,
                         cudaFuncAttributeMaxDynamicSharedMemorySize, SMEM_TOTAL);

    int grid = sms < num_tiles ? sms : num_tiles;
    LatentSpaceClustering_46797963657837_kernel<<<grid, TPB, SMEM_TOTAL>>>(
        x, c, (float*)d_out, n, num_tiles);
}